// round 5
// baseline (speedup 1.0000x reference)
#include <cuda_runtime.h>

// NeighborhoodAggregation via counting-sort + register reduction.
// out = (Z[node] + sum_{e: dst=node} Z[src_e]) / (deg(node)+1)
// Inputs: Z_real (100000*64 f32), Z_imag (100000*64 f32), edge_index (2*1600000 int32)
// Output: float32 [A_real ; A_imag]

#define MAX_NODES 100352
#define MAX_EDGES 1600000

__device__ int g_counts[MAX_NODES];   // in-degree (edges only)
__device__ int g_offsets[MAX_NODES];  // exclusive prefix of counts
__device__ int g_cursor[MAX_NODES];   // scatter cursors
__device__ int g_sorted[MAX_EDGES];   // src indices grouped by dst

// ---- Pass 0: zero counts ----
__global__ void zero_kernel(int n_nodes)
{
    int i = blockIdx.x * blockDim.x + threadIdx.x;
    if (i < n_nodes) g_counts[i] = 0;
}

// ---- Pass 1: histogram of dst ----
__global__ void hist_kernel(const int* __restrict__ dst, int n_edges)
{
    int i = blockIdx.x * blockDim.x + threadIdx.x;
    if (i < n_edges) atomicAdd(&g_counts[dst[i]], 1);
}

// ---- Pass 2: single-block exclusive scan over counts -> offsets, cursor ----
__global__ void scan_kernel(int n_nodes)
{
    __shared__ int ssum[1024];
    int t = threadIdx.x;
    int chunk = (n_nodes + 1023) / 1024;
    int begin = t * chunk;
    int end = begin + chunk; if (end > n_nodes) end = n_nodes;

    int s = 0;
    for (int i = begin; i < end; i++) s += g_counts[i];
    ssum[t] = s;
    __syncthreads();

    // Hillis-Steele inclusive scan over 1024 partials
    for (int off = 1; off < 1024; off <<= 1) {
        int v = (t >= off) ? ssum[t - off] : 0;
        __syncthreads();
        ssum[t] += v;
        __syncthreads();
    }

    int run = (t > 0) ? ssum[t - 1] : 0;  // exclusive base for this chunk
    for (int i = begin; i < end; i++) {
        g_offsets[i] = run;
        g_cursor[i] = run;
        run += g_counts[i];
    }
}

// ---- Pass 3: counting-sort scatter of src by dst ----
__global__ void scatter_kernel(const int* __restrict__ src,
                               const int* __restrict__ dst,
                               int n_edges)
{
    int i = blockIdx.x * blockDim.x + threadIdx.x;
    if (i >= n_edges) return;
    int d = dst[i];
    int pos = atomicAdd(&g_cursor[d], 1);
    g_sorted[pos] = src[i];
}

// ---- Pass 4: per-node register reduction (16 threads per node) ----
// Thread j of a node handles float4 chunk j of both real & imag rows.
__global__ void agg_kernel(const float4* __restrict__ zr,
                           const float4* __restrict__ zi,
                           float4* __restrict__ outr,
                           float4* __restrict__ outi,
                           int n_nodes)
{
    int t = blockIdx.x * blockDim.x + threadIdx.x;
    int node = t >> 4;
    int j = t & 15;
    if (node >= n_nodes) return;

    // self-loop contribution
    float4 ar = zr[(size_t)node * 16 + j];
    float4 ai = zi[(size_t)node * 16 + j];

    int base = g_offsets[node];
    int cnt = g_counts[node];

    int k = 0;
    for (; k + 1 < cnt; k += 2) {
        int s0 = g_sorted[base + k];
        int s1 = g_sorted[base + k + 1];
        float4 r0 = zr[(size_t)s0 * 16 + j];
        float4 i0 = zi[(size_t)s0 * 16 + j];
        float4 r1 = zr[(size_t)s1 * 16 + j];
        float4 i1 = zi[(size_t)s1 * 16 + j];
        ar.x += r0.x + r1.x; ar.y += r0.y + r1.y;
        ar.z += r0.z + r1.z; ar.w += r0.w + r1.w;
        ai.x += i0.x + i1.x; ai.y += i0.y + i1.y;
        ai.z += i0.z + i1.z; ai.w += i0.w + i1.w;
    }
    if (k < cnt) {
        int s0 = g_sorted[base + k];
        float4 r0 = zr[(size_t)s0 * 16 + j];
        float4 i0 = zi[(size_t)s0 * 16 + j];
        ar.x += r0.x; ar.y += r0.y; ar.z += r0.z; ar.w += r0.w;
        ai.x += i0.x; ai.y += i0.y; ai.z += i0.z; ai.w += i0.w;
    }

    float inv = 1.0f / (float)(cnt + 1);
    ar.x *= inv; ar.y *= inv; ar.z *= inv; ar.w *= inv;
    ai.x *= inv; ai.y *= inv; ai.z *= inv; ai.w *= inv;

    outr[(size_t)node * 16 + j] = ar;
    outi[(size_t)node * 16 + j] = ai;
}

extern "C" void kernel_launch(void* const* d_in, const int* in_sizes, int n_in,
                              void* d_out, int out_size)
{
    const float* Z_real = (const float*)d_in[0];
    const float* Z_imag = (const float*)d_in[1];
    const int* edge_index = (const int*)d_in[2];

    int n_nodes = in_sizes[0] / 64;
    int n_edges = in_sizes[2] / 2;

    const int* src = edge_index;
    const int* dst = edge_index + n_edges;

    float* out_real = (float*)d_out;
    float* out_imag = (float*)d_out + (size_t)n_nodes * 64;

    int threads = 256;

    zero_kernel<<<(n_nodes + threads - 1) / threads, threads>>>(n_nodes);
    hist_kernel<<<(n_edges + threads - 1) / threads, threads>>>(dst, n_edges);
    scan_kernel<<<1, 1024>>>(n_nodes);
    scatter_kernel<<<(n_edges + threads - 1) / threads, threads>>>(src, dst, n_edges);

    {
        long long total = (long long)n_nodes * 16;
        long long blocks = (total + threads - 1) / threads;
        agg_kernel<<<(unsigned)blocks, threads>>>((const float4*)Z_real, (const float4*)Z_imag,
                                                  (float4*)out_real, (float4*)out_imag, n_nodes);
    }
}

// round 6
// speedup vs baseline: 2.5163x; 2.5163x over previous
#include <cuda_runtime.h>

// NeighborhoodAggregation via counting-sort + warp-per-node register reduction.
// out = (Z[node] + sum_{e: dst=node} Z[src_e]) / (deg(node)+1)
// Inputs: Z_real (100000*64 f32), Z_imag (100000*64 f32), edge_index (2*1600000 int32)
// Output: float32 [A_real ; A_imag]

#define MAX_NODES 100352
#define MAX_EDGES 1600000
#define SCAN_BLOCK 256
#define SCAN_PER_THREAD 4
#define SCAN_TILE (SCAN_BLOCK * SCAN_PER_THREAD)   // 1024 elements per block
#define MAX_SCAN_BLOCKS 128                        // ceil(100352/1024) = 98

__device__ int g_counts[MAX_NODES];       // in-degree (edges only)
__device__ int g_offsets[MAX_NODES];      // exclusive prefix of counts
__device__ int g_cursor[MAX_NODES];       // scatter cursors
__device__ int g_sorted[MAX_EDGES];       // src indices grouped by dst
__device__ int g_blocksum[MAX_SCAN_BLOCKS];

// ---- Pass 0: zero counts ----
__global__ void zero_kernel(int n_nodes)
{
    int i = blockIdx.x * blockDim.x + threadIdx.x;
    if (i < n_nodes) g_counts[i] = 0;
}

// ---- Pass 1: histogram of dst ----
__global__ void hist_kernel(const int* __restrict__ dst, int n_edges)
{
    int i = blockIdx.x * blockDim.x + threadIdx.x;
    if (i < n_edges) atomicAdd(&g_counts[dst[i]], 1);
}

// ---- Pass 2a: per-block sums of counts (1024 elems / block) ----
__global__ void scan_blocksum_kernel(int n_nodes)
{
    __shared__ int sdata[SCAN_BLOCK];
    int t = threadIdx.x;
    int base = blockIdx.x * SCAN_TILE + t * SCAN_PER_THREAD;
    int s = 0;
#pragma unroll
    for (int q = 0; q < SCAN_PER_THREAD; q++) {
        int i = base + q;
        if (i < n_nodes) s += g_counts[i];
    }
    sdata[t] = s;
    __syncthreads();
    for (int off = SCAN_BLOCK / 2; off > 0; off >>= 1) {
        if (t < off) sdata[t] += sdata[t + off];
        __syncthreads();
    }
    if (t == 0) g_blocksum[blockIdx.x] = sdata[0];
}

// ---- Pass 2b: single small block scans the block sums (exclusive) ----
__global__ void scan_top_kernel(int n_blocks)
{
    __shared__ int sdata[MAX_SCAN_BLOCKS];
    int t = threadIdx.x;
    sdata[t] = (t < n_blocks) ? g_blocksum[t] : 0;
    __syncthreads();
    // Hillis-Steele inclusive
    for (int off = 1; off < MAX_SCAN_BLOCKS; off <<= 1) {
        int v = (t >= off) ? sdata[t - off] : 0;
        __syncthreads();
        sdata[t] += v;
        __syncthreads();
    }
    if (t < n_blocks) g_blocksum[t] = (t > 0) ? sdata[t - 1] : 0;  // exclusive
}

// ---- Pass 2c: per-block rescan, write offsets + cursor ----
__global__ void scan_write_kernel(int n_nodes)
{
    __shared__ int sdata[SCAN_BLOCK];
    int t = threadIdx.x;
    int base = blockIdx.x * SCAN_TILE + t * SCAN_PER_THREAD;

    int c[SCAN_PER_THREAD];
    int s = 0;
#pragma unroll
    for (int q = 0; q < SCAN_PER_THREAD; q++) {
        int i = base + q;
        c[q] = (i < n_nodes) ? g_counts[i] : 0;
        s += c[q];
    }
    sdata[t] = s;
    __syncthreads();
    // Hillis-Steele inclusive over per-thread sums
    for (int off = 1; off < SCAN_BLOCK; off <<= 1) {
        int v = (t >= off) ? sdata[t - off] : 0;
        __syncthreads();
        sdata[t] += v;
        __syncthreads();
    }
    int run = g_blocksum[blockIdx.x] + ((t > 0) ? sdata[t - 1] : 0);
#pragma unroll
    for (int q = 0; q < SCAN_PER_THREAD; q++) {
        int i = base + q;
        if (i < n_nodes) {
            g_offsets[i] = run;
            g_cursor[i] = run;
            run += c[q];
        }
    }
}

// ---- Pass 3: counting-sort scatter of src by dst ----
__global__ void scatter_kernel(const int* __restrict__ src,
                               const int* __restrict__ dst,
                               int n_edges)
{
    int i = blockIdx.x * blockDim.x + threadIdx.x;
    if (i >= n_edges) return;
    int d = dst[i];
    int pos = atomicAdd(&g_cursor[d], 1);
    g_sorted[pos] = src[i];
}

// ---- Pass 4: warp-per-node register reduction ----
// Lane l: l<16 -> real chunk l, l>=16 -> imag chunk l-16.
// Per edge, the full warp reads one 1KB row (512B real + 512B imag), coalesced.
// Indices are fetched 4-ahead at a warp-uniform address (broadcast).
__global__ void agg_kernel(const float4* __restrict__ zr,
                           const float4* __restrict__ zi,
                           float4* __restrict__ outr,
                           float4* __restrict__ outi,
                           int n_nodes)
{
    int warp_in_block = threadIdx.x >> 5;
    int node = blockIdx.x * (blockDim.x >> 5) + warp_in_block;
    if (node >= n_nodes) return;
    int lane = threadIdx.x & 31;

    const float4* __restrict__ zbase = (lane < 16) ? zr : zi;
    int chunk = lane & 15;

    // self-loop contribution
    float4 acc = zbase[(size_t)node * 16 + chunk];

    int base = g_offsets[node];
    int cnt = g_counts[node];
    const int* __restrict__ idx = g_sorted + base;

    int k = 0;
    for (; k + 4 <= cnt; k += 4) {
        // warp-uniform index loads (L1 broadcast), independent of each other
        int s0 = idx[k + 0];
        int s1 = idx[k + 1];
        int s2 = idx[k + 2];
        int s3 = idx[k + 3];
        float4 v0 = zbase[(size_t)s0 * 16 + chunk];
        float4 v1 = zbase[(size_t)s1 * 16 + chunk];
        float4 v2 = zbase[(size_t)s2 * 16 + chunk];
        float4 v3 = zbase[(size_t)s3 * 16 + chunk];
        acc.x += (v0.x + v1.x) + (v2.x + v3.x);
        acc.y += (v0.y + v1.y) + (v2.y + v3.y);
        acc.z += (v0.z + v1.z) + (v2.z + v3.z);
        acc.w += (v0.w + v1.w) + (v2.w + v3.w);
    }
    for (; k < cnt; k++) {
        int s0 = idx[k];
        float4 v0 = zbase[(size_t)s0 * 16 + chunk];
        acc.x += v0.x; acc.y += v0.y; acc.z += v0.z; acc.w += v0.w;
    }

    float inv = 1.0f / (float)(cnt + 1);
    acc.x *= inv; acc.y *= inv; acc.z *= inv; acc.w *= inv;

    float4* __restrict__ obase = (lane < 16) ? outr : outi;
    obase[(size_t)node * 16 + chunk] = acc;
}

extern "C" void kernel_launch(void* const* d_in, const int* in_sizes, int n_in,
                              void* d_out, int out_size)
{
    const float* Z_real = (const float*)d_in[0];
    const float* Z_imag = (const float*)d_in[1];
    const int* edge_index = (const int*)d_in[2];

    int n_nodes = in_sizes[0] / 64;
    int n_edges = in_sizes[2] / 2;

    const int* src = edge_index;
    const int* dst = edge_index + n_edges;

    float* out_real = (float*)d_out;
    float* out_imag = (float*)d_out + (size_t)n_nodes * 64;

    int threads = 256;
    int n_scan_blocks = (n_nodes + SCAN_TILE - 1) / SCAN_TILE;

    zero_kernel<<<(n_nodes + threads - 1) / threads, threads>>>(n_nodes);
    hist_kernel<<<(n_edges + threads - 1) / threads, threads>>>(dst, n_edges);
    scan_blocksum_kernel<<<n_scan_blocks, SCAN_BLOCK>>>(n_nodes);
    scan_top_kernel<<<1, MAX_SCAN_BLOCKS>>>(n_scan_blocks);
    scan_write_kernel<<<n_scan_blocks, SCAN_BLOCK>>>(n_nodes);
    scatter_kernel<<<(n_edges + threads - 1) / threads, threads>>>(src, dst, n_edges);

    {
        int warps_per_block = threads / 32;  // 8 nodes per block
        int blocks = (n_nodes + warps_per_block - 1) / warps_per_block;
        agg_kernel<<<blocks, threads>>>((const float4*)Z_real, (const float4*)Z_imag,
                                        (float4*)out_real, (float4*)out_imag, n_nodes);
    }
}